// round 15
// baseline (speedup 1.0000x reference)
#include <cuda_runtime.h>
#include <cuda_fp16.h>
#include <cstdint>

#define NN 100000
#define NN_PAD 100096          // multiple of 128
#define NE 1600000
#define DD 128
#define SPAD 136
#define CHUNK 50048            // = 391 * 128, chunk boundary for overlap

// ------------------------- scratch (device globals) ------------------------
__device__ __half g_X  [(size_t)NN_PAD * DD];  // fp16 features (ping)
__device__ __half g_Y  [(size_t)NN_PAD * DD];  // fp16 features (pong)
__device__ __half g_AGG[(size_t)NN_PAD * DD];  // fp16 aggregated (pad rows stay 0)
__device__ float  g_ns  [NN_PAD];              // norm_src (pad rows stay 0)
__device__ float  g_nd  [NN];
__device__ float  g_c   [NN_PAD];              // layer-2 fold coeffs (pads stay 0)
__device__ int    g_cnt2[2 * NN];              // [0,NN): src deg, [NN,2NN): dst deg
__device__ int    g_incl[NN];
__device__ int    g_cur [NN];
__device__ int    g_esrc[NE];
__device__ int    g_bsum[128];
__device__ float  g_vec [DD];
__device__ __half g_Wt0[DD * DD];              // W0^T fp16 [n][k]
__device__ __half g_Wt1[DD * DD];              // W1^T fp16 [n][k]

// ------------------------- histogram ---------------------------------------
__global__ void hist_kernel(const int* __restrict__ src,
                            const int* __restrict__ dst,
                            int* __restrict__ cnt2) {
    int i = blockIdx.x * blockDim.x + threadIdx.x;
    if (i < NE) {
        atomicAdd(&cnt2[src[i]], 1);
        atomicAdd(&cnt2[NN + dst[i]], 1);
    }
}

// ------------------------- degree norms ------------------------------------
__global__ void norm_kernel(const int* __restrict__ cnt2,
                            float* __restrict__ ns, float* __restrict__ nd) {
    int i = blockIdx.x * blockDim.x + threadIdx.x;
    if (i < NN) {
        ns[i] = rsqrtf(fmaxf((float)cnt2[i], 1.0f));
        nd[i] = rsqrtf(fmaxf((float)cnt2[NN + i], 1.0f));
    }
}

// ------------------------- scan (chunk=1024) -------------------------------
__global__ void scan1_kernel(const int* __restrict__ cnt,
                             int* __restrict__ incl, int* __restrict__ bsum) {
    __shared__ int s[256];
    int b = blockIdx.x, t = threadIdx.x;
    int base = b * 1024 + t * 4;
    int v0 = (base + 0 < NN) ? cnt[base + 0] : 0;
    int v1 = (base + 1 < NN) ? cnt[base + 1] : 0;
    int v2 = (base + 2 < NN) ? cnt[base + 2] : 0;
    int v3 = (base + 3 < NN) ? cnt[base + 3] : 0;
    int l1 = v0 + v1, l2 = l1 + v2, l3 = l2 + v3;
    s[t] = l3;
    __syncthreads();
    for (int off = 1; off < 256; off <<= 1) {
        int x = (t >= off) ? s[t - off] : 0;
        __syncthreads();
        s[t] += x;
        __syncthreads();
    }
    int prev = t ? s[t - 1] : 0;
    if (base + 0 < NN) incl[base + 0] = prev + v0;
    if (base + 1 < NN) incl[base + 1] = prev + l1;
    if (base + 2 < NN) incl[base + 2] = prev + l2;
    if (base + 3 < NN) incl[base + 3] = prev + l3;
    if (t == 255) bsum[b] = s[255];
}

// finalize incl + cursors; each block computes its own chunk-prefix of bsum
__global__ void scan3_kernel(int* __restrict__ incl, const int* __restrict__ bsum,
                             const int* __restrict__ cnt2, int* __restrict__ cur) {
    __shared__ int red[256];
    int b = blockIdx.x, t = threadIdx.x;
    red[t] = (t < b) ? bsum[t] : 0;     // b <= 97 < 256
    __syncthreads();
    for (int off = 128; off > 0; off >>= 1) {
        if (t < off) red[t] += red[t + off];
        __syncthreads();
    }
    int offset = red[0];
    int base = b * 1024 + t * 4;
#pragma unroll
    for (int j = 0; j < 4; j++) {
        int i = base + j;
        if (i < NN) {
            int v = incl[i] + offset;
            incl[i] = v;
            cur[i]  = v - cnt2[NN + i];
        }
    }
}

// CSR fill + layer-2 fold coefficient c[src] += nd[dst]
__global__ void fill_kernel(const int* __restrict__ src, const int* __restrict__ dst,
                            const float* __restrict__ nd,
                            int* __restrict__ cur, int* __restrict__ esrc,
                            float* __restrict__ c) {
    int i = blockIdx.x * blockDim.x + threadIdx.x;
    if (i < NE) {
        int s = src[i], d = dst[i];
        int pos = atomicAdd(&cur[d], 1);
        esrc[pos] = s;
        atomicAdd(&c[s], nd[d]);
    }
}

// ------------------------- h -> fp16 prescaled by ns -----------------------
__global__ void conv_kernel(const float* __restrict__ h,
                            const float* __restrict__ ns,
                            __half* __restrict__ X) {
    int i = blockIdx.x * blockDim.x + threadIdx.x;   // float4 index
    if (i < NN * DD / 4) {
        int row = i >> 5;
        float s = ns[row];
        float4 v = ((const float4*)h)[i];
        __half2 a = __floats2half2_rn(v.x * s, v.y * s);
        __half2 b = __floats2half2_rn(v.z * s, v.w * s);
        uint2 u;
        u.x = *(uint32_t*)&a;
        u.y = *(uint32_t*)&b;
        ((uint2*)X)[i] = u;
    }
}

// ------------------------- W0,W1 -> W^T fp16 -------------------------------
__global__ void prep_kernel(const float* __restrict__ W0, const float* __restrict__ W1,
                            __half* __restrict__ Wt0, __half* __restrict__ Wt1) {
    int i = blockIdx.x * blockDim.x + threadIdx.x;
    if (i < DD * DD) {
        int k = i >> 7, n = i & 127;
        Wt0[n * DD + k] = __float2half(W0[i]);
        Wt1[n * DD + k] = __float2half(W1[i]);
    }
}

// ------------------------- gather SpMM (half2 accumulation) ----------------
// Processes nodes [n0, n1). Warp per node, 8 edges/iter, HADD2 accumulation.
__global__ void gather_kernel(const __half* __restrict__ Xh,
                              const float* __restrict__ nd,
                              const int* __restrict__ incl,
                              const int* __restrict__ cnt2,
                              const int* __restrict__ esrc,
                              __half* __restrict__ outp,
                              int n0, int n1) {
    const int lane  = threadIdx.x & 31;
    const int pr    = lane >> 4;          // 0 or 1
    const int li    = lane & 15;          // 0..15
    const int warp0 = (blockIdx.x * blockDim.x + threadIdx.x) >> 5;
    const int nwarp = (gridDim.x * blockDim.x) >> 5;
    const uint4* __restrict__ Xv = (const uint4*)Xh;   // 16 x uint4 per row

    for (int node = n0 + warp0; node < n1; node += nwarp) {
        int end = incl[node];
        int beg = end - cnt2[NN + node];
        __half2 acc0 = __float2half2_rn(0.f);
        __half2 acc1 = acc0, acc2 = acc0, acc3 = acc0;

#define ACC4(u) { \
        acc0 = __hadd2(acc0, *(__half2*)&(u).x); \
        acc1 = __hadd2(acc1, *(__half2*)&(u).y); \
        acc2 = __hadd2(acc2, *(__half2*)&(u).z); \
        acc3 = __hadd2(acc3, *(__half2*)&(u).w); }

        int e = beg;
        for (; e + 8 <= end; e += 8) {
            int sA = esrc[e + 0 + pr];
            int sB = esrc[e + 2 + pr];
            int sC = esrc[e + 4 + pr];
            int sD = esrc[e + 6 + pr];
            uint4 uA = Xv[(size_t)sA * 16 + li];
            uint4 uB = Xv[(size_t)sB * 16 + li];
            uint4 uC = Xv[(size_t)sC * 16 + li];
            uint4 uD = Xv[(size_t)sD * 16 + li];
            ACC4(uA) ACC4(uB) ACC4(uC) ACC4(uD)
        }
        for (; e < end; e += 2) {
            int idx = e + pr;
            if (idx < end) {
                int s = esrc[idx];
                uint4 u = Xv[(size_t)s * 16 + li];
                ACC4(u)
            }
        }
#undef ACC4
        acc0 = __hadd2(acc0, __shfl_xor_sync(0xffffffff, acc0, 16));
        acc1 = __hadd2(acc1, __shfl_xor_sync(0xffffffff, acc1, 16));
        acc2 = __hadd2(acc2, __shfl_xor_sync(0xffffffff, acc2, 16));
        acc3 = __hadd2(acc3, __shfl_xor_sync(0xffffffff, acc3, 16));

        if (pr == 0) {
            float sd = nd[node];
            float2 f0 = __half22float2(acc0);
            float2 f1 = __half22float2(acc1);
            float2 f2 = __half22float2(acc2);
            float2 f3 = __half22float2(acc3);
            __half2 h0 = __floats2half2_rn(f0.x * sd, f0.y * sd);
            __half2 h1 = __floats2half2_rn(f1.x * sd, f1.y * sd);
            __half2 h2 = __floats2half2_rn(f2.x * sd, f2.y * sd);
            __half2 h3 = __floats2half2_rn(f3.x * sd, f3.y * sd);
            uint4 u;
            u.x = *(uint32_t*)&h0; u.y = *(uint32_t*)&h1;
            u.z = *(uint32_t*)&h2; u.w = *(uint32_t*)&h3;
            ((uint4*)outp)[(size_t)node * 16 + li] = u;
        }
    }
}

// ------------------------- fp16 MMA GEMM core ------------------------------
__device__ __forceinline__ void mma_f16(float* d, const uint32_t* a, const uint32_t* b) {
    asm volatile("mma.sync.aligned.m16n8k16.row.col.f32.f16.f16.f32 "
                 "{%0,%1,%2,%3}, {%4,%5,%6,%7}, {%8,%9}, {%0,%1,%2,%3};"
                 : "+f"(d[0]), "+f"(d[1]), "+f"(d[2]), "+f"(d[3])
                 : "r"(a[0]), "r"(a[1]), "r"(a[2]), "r"(a[3]),
                   "r"(b[0]), "r"(b[1]));
}

// FINAL=0: Out[r,:] = half( relu(A[r,:]@W + b) * ns[r] )
// FINAL=1: vec[c] += sum_r ns[r]*cf[r]*relu(A[r,:]@W + b)[c]
// rowBase: starting row of this launch's tile range.
template <int FINAL>
__global__ __launch_bounds__(256)
void gemm_f16_kernel(const __half* __restrict__ A,
                     const __half* __restrict__ Wt, const float* __restrict__ bias,
                     const float* __restrict__ ns, const float* __restrict__ cf,
                     __half* __restrict__ Out, float* __restrict__ vec,
                     int rowBase) {
    extern __shared__ __half smem[];
    __half (*As)[SPAD]  = (__half(*)[SPAD])smem;
    __half (*Wsh)[SPAD] = (__half(*)[SPAD])(smem + 128 * SPAD);
    __shared__ float sv[DD];

    const int t    = threadIdx.x;
    const int lane = t & 31;
    const int warp = t >> 5;
    const int row0 = rowBase + blockIdx.x * 128;

    if (FINAL && t < DD) sv[t] = 0.0f;

#pragma unroll
    for (int j = 0; j < 8; j++) {
        int id = t + j * 256;
        int r  = id >> 4;
        int c8 = (id & 15) * 8;
        *(uint4*)&As[r][c8]  = *(const uint4*)(A  + (size_t)(row0 + r) * DD + c8);
        *(uint4*)&Wsh[r][c8] = *(const uint4*)(Wt + (size_t)r * DD + c8);
    }
    __syncthreads();

    const int wm = (warp & 3) * 32;
    const int wn = (warp >> 2) * 64;
    const int g  = lane >> 2;
    const int tg = (lane & 3) * 2;

    float acc[2][8][4];
#pragma unroll
    for (int m = 0; m < 2; m++)
#pragma unroll
        for (int f = 0; f < 8; f++)
#pragma unroll
            for (int i = 0; i < 4; i++) acc[m][f][i] = 0.0f;

#pragma unroll
    for (int ks = 0; ks < 8; ks++) {
        const int k0 = ks * 16;
        uint32_t a[2][4];
#pragma unroll
        for (int m = 0; m < 2; m++) {
            int r = wm + m * 16 + g;
            a[m][0] = *(const uint32_t*)&As[r][k0 + tg];
            a[m][1] = *(const uint32_t*)&As[r + 8][k0 + tg];
            a[m][2] = *(const uint32_t*)&As[r][k0 + tg + 8];
            a[m][3] = *(const uint32_t*)&As[r + 8][k0 + tg + 8];
        }
        uint32_t b[8][2];
#pragma unroll
        for (int f = 0; f < 8; f++) {
            int n = wn + f * 8 + g;
            b[f][0] = *(const uint32_t*)&Wsh[n][k0 + tg];
            b[f][1] = *(const uint32_t*)&Wsh[n][k0 + tg + 8];
        }
#pragma unroll
        for (int m = 0; m < 2; m++)
#pragma unroll
            for (int f = 0; f < 8; f++)
                mma_f16(acc[m][f], a[m], b[f]);
    }

#pragma unroll
    for (int m = 0; m < 2; m++) {
        int ra = row0 + wm + m * 16 + g;
        int rb = ra + 8;
        float sa = ns[ra];
        float sb = ns[rb];
        if (FINAL) { sa *= cf[ra]; sb *= cf[rb]; }
#pragma unroll
        for (int f = 0; f < 8; f++) {
            int n  = wn + f * 8 + tg;
            float b0 = __ldg(bias + n);
            float b1 = __ldg(bias + n + 1);
            float v0 = fmaxf(acc[m][f][0] + b0, 0.0f) * sa;
            float v1 = fmaxf(acc[m][f][1] + b1, 0.0f) * sa;
            float v2 = fmaxf(acc[m][f][2] + b0, 0.0f) * sb;
            float v3 = fmaxf(acc[m][f][3] + b1, 0.0f) * sb;
            if (!FINAL) {
                *(__half2*)(Out + (size_t)ra * DD + n) = __floats2half2_rn(v0, v1);
                *(__half2*)(Out + (size_t)rb * DD + n) = __floats2half2_rn(v2, v3);
            } else {
                float c0 = v0 + v2;
                float c1 = v1 + v3;
#pragma unroll
                for (int o = 4; o < 32; o <<= 1) {
                    c0 += __shfl_xor_sync(0xffffffff, c0, o);
                    c1 += __shfl_xor_sync(0xffffffff, c1, o);
                }
                if (g == 0) {
                    atomicAdd(&sv[n], c0);
                    atomicAdd(&sv[n + 1], c1);
                }
            }
        }
    }

    if (FINAL) {
        __syncthreads();
        if (t < DD) atomicAdd(&vec[t], sv[t]);
    }
}

// ------------------------- final micro-GEMM: out = (vec/N) @ W2 + b2 -------
__global__ void final_kernel(const float* __restrict__ W2,
                             const float* __restrict__ b2,
                             const float* __restrict__ vec,
                             float* __restrict__ out) {
    __shared__ float v[DD];
    int c = threadIdx.x;
    v[c] = vec[c] * (1.0f / (float)NN);
    __syncthreads();
    float acc = b2[c];
#pragma unroll 8
    for (int k = 0; k < DD; k++)
        acc = fmaf(v[k], W2[(size_t)k * DD + c], acc);
    out[c] = acc;
}

// ------------------------- stream/event infra (created at load time) -------
static cudaStream_t g_s2 = nullptr;
static cudaEvent_t  g_ev[8] = {};
static bool g_infraTried = false;

static void ensure_infra() {
    if (g_infraTried) return;
    g_infraTried = true;
    cudaStreamCreateWithFlags(&g_s2, cudaStreamNonBlocking);
    for (int i = 0; i < 8; i++)
        cudaEventCreateWithFlags(&g_ev[i], cudaEventDisableTiming);
}

namespace { struct InfraInit { InfraInit() { ensure_infra(); } } g_infraInit; }

// ===========================================================================
extern "C" void kernel_launch(void* const* d_in, const int* in_sizes, int n_in,
                              void* d_out, int out_size) {
    const float* h   = (const float*)d_in[0];
    const int*   src = (const int*)d_in[1];   // JAX demotes int64 -> int32
    const int*   dst = (const int*)d_in[2];
    const float* W0 = (const float*)d_in[3];
    const float* b0 = (const float*)d_in[4];
    const float* W1 = (const float*)d_in[5];
    const float* b1 = (const float*)d_in[6];
    const float* W2 = (const float*)d_in[7];
    const float* b2 = (const float*)d_in[8];
    float* out = (float*)d_out;

    void *pX, *pY, *pAGG, *pns, *pnd, *pc, *pcnt2, *pincl, *pcur, *pesrc,
         *pbsum, *pvec, *pWt0, *pWt1;
    cudaGetSymbolAddress(&pX,    g_X);
    cudaGetSymbolAddress(&pY,    g_Y);
    cudaGetSymbolAddress(&pAGG,  g_AGG);
    cudaGetSymbolAddress(&pns,   g_ns);
    cudaGetSymbolAddress(&pnd,   g_nd);
    cudaGetSymbolAddress(&pc,    g_c);
    cudaGetSymbolAddress(&pcnt2, g_cnt2);
    cudaGetSymbolAddress(&pincl, g_incl);
    cudaGetSymbolAddress(&pcur,  g_cur);
    cudaGetSymbolAddress(&pesrc, g_esrc);
    cudaGetSymbolAddress(&pbsum, g_bsum);
    cudaGetSymbolAddress(&pvec,  g_vec);
    cudaGetSymbolAddress(&pWt0,  g_Wt0);
    cudaGetSymbolAddress(&pWt1,  g_Wt1);
    __half* X    = (__half*)pX;
    __half* Y    = (__half*)pY;
    __half* AGG  = (__half*)pAGG;
    float*  ns   = (float*)pns;
    float*  nd   = (float*)pnd;
    float*  cf   = (float*)pc;
    int*    cnt2 = (int*)pcnt2;
    int*    incl = (int*)pincl;
    int*    cur  = (int*)pcur;
    int*    esrc = (int*)pesrc;
    int*    bsum = (int*)pbsum;
    float*  vec  = (float*)pvec;
    __half* Wt0  = (__half*)pWt0;
    __half* Wt1  = (__half*)pWt1;

    static int smemSet = 0;
    const int gemmSmem = 2 * 128 * SPAD * sizeof(__half);   // 69632 B
    if (!smemSet) {
        cudaFuncSetAttribute(gemm_f16_kernel<0>,
                             cudaFuncAttributeMaxDynamicSharedMemorySize, gemmSmem);
        cudaFuncSetAttribute(gemm_f16_kernel<1>,
                             cudaFuncAttributeMaxDynamicSharedMemorySize, gemmSmem);
        smemSet = 1;
    }

    bool fork = (g_s2 != nullptr);
    if (fork) for (int i = 0; i < 8; i++) if (!g_ev[i]) fork = false;
    const int nScanBlocks = (NN + 1023) / 1024;   // 98

    // --- degrees ---
    cudaMemsetAsync(cnt2, 0, 2 * NN * sizeof(int));
    cudaMemsetAsync(cf, 0, NN * sizeof(float));
    hist_kernel<<<(NE + 255) / 256, 256>>>(src, dst, cnt2);

    if (fork) {
        cudaEventRecord(g_ev[0], 0);
        cudaStreamWaitEvent(g_s2, g_ev[0], 0);
        norm_kernel<<<(NN + 255) / 256, 256, 0, g_s2>>>(cnt2, ns, nd);
        cudaEventRecord(g_ev[1], g_s2);
        conv_kernel<<<(NN * DD / 4 + 255) / 256, 256, 0, g_s2>>>(h, ns, X);
        prep_kernel<<<64, 256, 0, g_s2>>>(W0, W1, Wt0, Wt1);
        cudaEventRecord(g_ev[2], g_s2);
    } else {
        norm_kernel<<<(NN + 255) / 256, 256>>>(cnt2, ns, nd);
        conv_kernel<<<(NN * DD / 4 + 255) / 256, 256>>>(h, ns, X);
        prep_kernel<<<64, 256>>>(W0, W1, Wt0, Wt1);
    }

    // --- CSR chain on main stream ---
    scan1_kernel<<<nScanBlocks, 256>>>(cnt2 + NN, incl, bsum);
    scan3_kernel<<<nScanBlocks, 256>>>(incl, bsum, cnt2, cur);
    if (fork) cudaStreamWaitEvent(0, g_ev[1], 0);   // fill needs nd
    fill_kernel<<<(NE + 255) / 256, 256>>>(src, dst, nd, cur, esrc, cf);
    if (fork) cudaStreamWaitEvent(0, g_ev[2], 0);   // gather0 needs X, gemm needs Wt

    const int gB0 = (CHUNK * 32 + 255) / 256;            // chunk-0 gather blocks
    const int gB1 = ((NN - CHUNK) * 32 + 255) / 256;     // chunk-1 gather blocks
    const int mB0 = CHUNK / 128;                          // 391
    const int mB1 = (NN_PAD - CHUNK) / 128;               // 391

    if (fork) {
        // ---- layer 0: chunked overlap ----
        gather_kernel<<<gB0, 256>>>(X, nd, incl, cnt2, esrc, AGG, 0, CHUNK);
        cudaEventRecord(g_ev[3], 0);
        gather_kernel<<<gB1, 256>>>(X, nd, incl, cnt2, esrc, AGG, CHUNK, NN);
        cudaStreamWaitEvent(g_s2, g_ev[3], 0);
        gemm_f16_kernel<0><<<mB0, 256, gemmSmem, g_s2>>>(AGG, Wt0, b0, ns, cf, Y, vec, 0);
        cudaEventRecord(g_ev[4], g_s2);
        gemm_f16_kernel<0><<<mB1, 256, gemmSmem>>>(AGG, Wt0, b0, ns, cf, Y, vec, CHUNK);
        cudaStreamWaitEvent(0, g_ev[4], 0);   // all of Y ready

        // ---- layer 1 + folded layer 2: chunked overlap ----
        gather_kernel<<<gB0, 256>>>(Y, nd, incl, cnt2, esrc, AGG, 0, CHUNK);
        cudaMemsetAsync(vec, 0, DD * sizeof(float));
        cudaEventRecord(g_ev[5], 0);          // covers gather chunk0 + vec clear
        gather_kernel<<<gB1, 256>>>(Y, nd, incl, cnt2, esrc, AGG, CHUNK, NN);
        cudaStreamWaitEvent(g_s2, g_ev[5], 0);
        gemm_f16_kernel<1><<<mB0, 256, gemmSmem, g_s2>>>(AGG, Wt1, b1, ns, cf, X, vec, 0);
        cudaEventRecord(g_ev[6], g_s2);
        gemm_f16_kernel<1><<<mB1, 256, gemmSmem>>>(AGG, Wt1, b1, ns, cf, X, vec, CHUNK);
        cudaStreamWaitEvent(0, g_ev[6], 0);
    } else {
        gather_kernel<<<gB0 + gB1, 256>>>(X, nd, incl, cnt2, esrc, AGG, 0, NN);
        gemm_f16_kernel<0><<<NN_PAD / 128, 256, gemmSmem>>>(AGG, Wt0, b0, ns, cf, Y, vec, 0);
        gather_kernel<<<gB0 + gB1, 256>>>(Y, nd, incl, cnt2, esrc, AGG, 0, NN);
        cudaMemsetAsync(vec, 0, DD * sizeof(float));
        gemm_f16_kernel<1><<<NN_PAD / 128, 256, gemmSmem>>>(AGG, Wt1, b1, ns, cf, X, vec, 0);
    }

    // --- out = (vec/N) @ W2 + b2 ---
    final_kernel<<<1, DD>>>(W2, b2, vec, out);

    (void)in_sizes; (void)n_in; (void)out_size;
}

// round 16
// speedup vs baseline: 1.3799x; 1.3799x over previous
#include <cuda_runtime.h>
#include <cuda_fp16.h>
#include <cstdint>

#define NN 100000
#define NN_PAD 100096          // multiple of 128
#define NE 1600000
#define DD 128
#define SPAD 136

// ------------------------- scratch (device globals) ------------------------
__device__ __half g_X  [(size_t)NN_PAD * DD];  // fp16 features (ping)
__device__ __half g_Y  [(size_t)NN_PAD * DD];  // fp16 features (pong)
__device__ __half g_AGG[(size_t)NN_PAD * DD];  // fp16 aggregated (pad rows stay 0)
__device__ float  g_ns  [NN_PAD];              // norm_src (pad rows stay 0)
__device__ float  g_nd  [NN];
__device__ float  g_c   [NN_PAD];              // layer-2 fold coeffs (pads stay 0)
__device__ int    g_cnt2[2 * NN];              // [0,NN): src deg, [NN,2NN): dst deg
__device__ int    g_incl[NN];
__device__ int    g_cur [NN];
__device__ int    g_esrc[NE];
__device__ int    g_bsum[128];
__device__ float  g_vec [DD];
__device__ __half g_Wt0[DD * DD];              // W0^T fp16 [n][k]
__device__ __half g_Wt1[DD * DD];              // W1^T fp16 [n][k]

// ------------------------- histogram ---------------------------------------
__global__ void hist_kernel(const int* __restrict__ src,
                            const int* __restrict__ dst,
                            int* __restrict__ cnt2) {
    int i = blockIdx.x * blockDim.x + threadIdx.x;
    if (i < NE) {
        atomicAdd(&cnt2[src[i]], 1);
        atomicAdd(&cnt2[NN + dst[i]], 1);
    }
}

// ------------------------- degree norms ------------------------------------
__global__ void norm_kernel(const int* __restrict__ cnt2,
                            float* __restrict__ ns, float* __restrict__ nd) {
    int i = blockIdx.x * blockDim.x + threadIdx.x;
    if (i < NN) {
        ns[i] = rsqrtf(fmaxf((float)cnt2[i], 1.0f));
        nd[i] = rsqrtf(fmaxf((float)cnt2[NN + i], 1.0f));
    }
}

// ------------------------- layer-2 fold coefficients -----------------------
// c[src] += nd[dst]  (independent of the CSR scan chain; runs on side stream)
__global__ void cf_kernel(const int* __restrict__ src, const int* __restrict__ dst,
                          const float* __restrict__ nd, float* __restrict__ c) {
    int i = blockIdx.x * blockDim.x + threadIdx.x;
    if (i < NE)
        atomicAdd(&c[src[i]], nd[dst[i]]);
}

// ------------------------- scan (chunk=1024) -------------------------------
__global__ void scan1_kernel(const int* __restrict__ cnt,
                             int* __restrict__ incl, int* __restrict__ bsum) {
    __shared__ int s[256];
    int b = blockIdx.x, t = threadIdx.x;
    int base = b * 1024 + t * 4;
    int v0 = (base + 0 < NN) ? cnt[base + 0] : 0;
    int v1 = (base + 1 < NN) ? cnt[base + 1] : 0;
    int v2 = (base + 2 < NN) ? cnt[base + 2] : 0;
    int v3 = (base + 3 < NN) ? cnt[base + 3] : 0;
    int l1 = v0 + v1, l2 = l1 + v2, l3 = l2 + v3;
    s[t] = l3;
    __syncthreads();
    for (int off = 1; off < 256; off <<= 1) {
        int x = (t >= off) ? s[t - off] : 0;
        __syncthreads();
        s[t] += x;
        __syncthreads();
    }
    int prev = t ? s[t - 1] : 0;
    if (base + 0 < NN) incl[base + 0] = prev + v0;
    if (base + 1 < NN) incl[base + 1] = prev + l1;
    if (base + 2 < NN) incl[base + 2] = prev + l2;
    if (base + 3 < NN) incl[base + 3] = prev + l3;
    if (t == 255) bsum[b] = s[255];
}

// finalize incl + cursors; each block computes its own chunk-prefix of bsum
__global__ void scan3_kernel(int* __restrict__ incl, const int* __restrict__ bsum,
                             const int* __restrict__ cnt2, int* __restrict__ cur) {
    __shared__ int red[256];
    int b = blockIdx.x, t = threadIdx.x;
    red[t] = (t < b) ? bsum[t] : 0;     // b <= 97 < 256
    __syncthreads();
    for (int off = 128; off > 0; off >>= 1) {
        if (t < off) red[t] += red[t + off];
        __syncthreads();
    }
    int offset = red[0];
    int base = b * 1024 + t * 4;
#pragma unroll
    for (int j = 0; j < 4; j++) {
        int i = base + j;
        if (i < NN) {
            int v = incl[i] + offset;
            incl[i] = v;
            cur[i]  = v - cnt2[NN + i];
        }
    }
}

// CSR fill (cf accumulation moved to cf_kernel)
__global__ void fill_kernel(const int* __restrict__ src, const int* __restrict__ dst,
                            int* __restrict__ cur, int* __restrict__ esrc) {
    int i = blockIdx.x * blockDim.x + threadIdx.x;
    if (i < NE) {
        int pos = atomicAdd(&cur[dst[i]], 1);
        esrc[pos] = src[i];
    }
}

// ------------------------- h -> fp16 prescaled by ns -----------------------
__global__ void conv_kernel(const float* __restrict__ h,
                            const float* __restrict__ ns,
                            __half* __restrict__ X) {
    int i = blockIdx.x * blockDim.x + threadIdx.x;   // float4 index
    if (i < NN * DD / 4) {
        int row = i >> 5;
        float s = ns[row];
        float4 v = ((const float4*)h)[i];
        __half2 a = __floats2half2_rn(v.x * s, v.y * s);
        __half2 b = __floats2half2_rn(v.z * s, v.w * s);
        uint2 u;
        u.x = *(uint32_t*)&a;
        u.y = *(uint32_t*)&b;
        ((uint2*)X)[i] = u;
    }
}

// ------------------------- W0,W1 -> W^T fp16 -------------------------------
__global__ void prep_kernel(const float* __restrict__ W0, const float* __restrict__ W1,
                            __half* __restrict__ Wt0, __half* __restrict__ Wt1) {
    int i = blockIdx.x * blockDim.x + threadIdx.x;
    if (i < DD * DD) {
        int k = i >> 7, n = i & 127;
        Wt0[n * DD + k] = __float2half(W0[i]);
        Wt1[n * DD + k] = __float2half(W1[i]);
    }
}

// ------------------------- gather SpMM (half2 accumulation) ----------------
__global__ void gather_kernel(const __half* __restrict__ Xh,
                              const float* __restrict__ nd,
                              const int* __restrict__ incl,
                              const int* __restrict__ cnt2,
                              const int* __restrict__ esrc,
                              __half* __restrict__ outp) {
    const int lane  = threadIdx.x & 31;
    const int pr    = lane >> 4;          // 0 or 1
    const int li    = lane & 15;          // 0..15
    const int warp0 = (blockIdx.x * blockDim.x + threadIdx.x) >> 5;
    const int nwarp = (gridDim.x * blockDim.x) >> 5;
    const uint4* __restrict__ Xv = (const uint4*)Xh;   // 16 x uint4 per row

    for (int node = warp0; node < NN; node += nwarp) {
        int end = incl[node];
        int beg = end - cnt2[NN + node];
        __half2 acc0 = __float2half2_rn(0.f);
        __half2 acc1 = acc0, acc2 = acc0, acc3 = acc0;

#define ACC4(u) { \
        acc0 = __hadd2(acc0, *(__half2*)&(u).x); \
        acc1 = __hadd2(acc1, *(__half2*)&(u).y); \
        acc2 = __hadd2(acc2, *(__half2*)&(u).z); \
        acc3 = __hadd2(acc3, *(__half2*)&(u).w); }

        int e = beg;
        for (; e + 8 <= end; e += 8) {
            int sA = esrc[e + 0 + pr];
            int sB = esrc[e + 2 + pr];
            int sC = esrc[e + 4 + pr];
            int sD = esrc[e + 6 + pr];
            uint4 uA = Xv[(size_t)sA * 16 + li];
            uint4 uB = Xv[(size_t)sB * 16 + li];
            uint4 uC = Xv[(size_t)sC * 16 + li];
            uint4 uD = Xv[(size_t)sD * 16 + li];
            ACC4(uA) ACC4(uB) ACC4(uC) ACC4(uD)
        }
        for (; e < end; e += 2) {
            int idx = e + pr;
            if (idx < end) {
                int s = esrc[idx];
                uint4 u = Xv[(size_t)s * 16 + li];
                ACC4(u)
            }
        }
#undef ACC4
        acc0 = __hadd2(acc0, __shfl_xor_sync(0xffffffff, acc0, 16));
        acc1 = __hadd2(acc1, __shfl_xor_sync(0xffffffff, acc1, 16));
        acc2 = __hadd2(acc2, __shfl_xor_sync(0xffffffff, acc2, 16));
        acc3 = __hadd2(acc3, __shfl_xor_sync(0xffffffff, acc3, 16));

        if (pr == 0) {
            float sd = nd[node];
            float2 f0 = __half22float2(acc0);
            float2 f1 = __half22float2(acc1);
            float2 f2 = __half22float2(acc2);
            float2 f3 = __half22float2(acc3);
            __half2 h0 = __floats2half2_rn(f0.x * sd, f0.y * sd);
            __half2 h1 = __floats2half2_rn(f1.x * sd, f1.y * sd);
            __half2 h2 = __floats2half2_rn(f2.x * sd, f2.y * sd);
            __half2 h3 = __floats2half2_rn(f3.x * sd, f3.y * sd);
            uint4 u;
            u.x = *(uint32_t*)&h0; u.y = *(uint32_t*)&h1;
            u.z = *(uint32_t*)&h2; u.w = *(uint32_t*)&h3;
            ((uint4*)outp)[(size_t)node * 16 + li] = u;
        }
    }
}

// ------------------------- fp16 MMA GEMM core ------------------------------
__device__ __forceinline__ void mma_f16(float* d, const uint32_t* a, const uint32_t* b) {
    asm volatile("mma.sync.aligned.m16n8k16.row.col.f32.f16.f16.f32 "
                 "{%0,%1,%2,%3}, {%4,%5,%6,%7}, {%8,%9}, {%0,%1,%2,%3};"
                 : "+f"(d[0]), "+f"(d[1]), "+f"(d[2]), "+f"(d[3])
                 : "r"(a[0]), "r"(a[1]), "r"(a[2]), "r"(a[3]),
                   "r"(b[0]), "r"(b[1]));
}

// FINAL=0: Out[r,:] = half( relu(A[r,:]@W + b) * ns[r] )
// FINAL=1: vec[c] += sum_r ns[r]*cf[r]*relu(A[r,:]@W + b)[c]
template <int FINAL>
__global__ __launch_bounds__(256)
void gemm_f16_kernel(const __half* __restrict__ A,
                     const __half* __restrict__ Wt, const float* __restrict__ bias,
                     const float* __restrict__ ns, const float* __restrict__ cf,
                     __half* __restrict__ Out, float* __restrict__ vec) {
    extern __shared__ __half smem[];
    __half (*As)[SPAD]  = (__half(*)[SPAD])smem;
    __half (*Wsh)[SPAD] = (__half(*)[SPAD])(smem + 128 * SPAD);
    __shared__ float sv[DD];

    const int t    = threadIdx.x;
    const int lane = t & 31;
    const int warp = t >> 5;
    const int row0 = blockIdx.x * 128;

    if (FINAL && t < DD) sv[t] = 0.0f;

#pragma unroll
    for (int j = 0; j < 8; j++) {
        int id = t + j * 256;
        int r  = id >> 4;
        int c8 = (id & 15) * 8;
        *(uint4*)&As[r][c8]  = *(const uint4*)(A  + (size_t)(row0 + r) * DD + c8);
        *(uint4*)&Wsh[r][c8] = *(const uint4*)(Wt + (size_t)r * DD + c8);
    }
    __syncthreads();

    const int wm = (warp & 3) * 32;
    const int wn = (warp >> 2) * 64;
    const int g  = lane >> 2;
    const int tg = (lane & 3) * 2;

    float acc[2][8][4];
#pragma unroll
    for (int m = 0; m < 2; m++)
#pragma unroll
        for (int f = 0; f < 8; f++)
#pragma unroll
            for (int i = 0; i < 4; i++) acc[m][f][i] = 0.0f;

#pragma unroll
    for (int ks = 0; ks < 8; ks++) {
        const int k0 = ks * 16;
        uint32_t a[2][4];
#pragma unroll
        for (int m = 0; m < 2; m++) {
            int r = wm + m * 16 + g;
            a[m][0] = *(const uint32_t*)&As[r][k0 + tg];
            a[m][1] = *(const uint32_t*)&As[r + 8][k0 + tg];
            a[m][2] = *(const uint32_t*)&As[r][k0 + tg + 8];
            a[m][3] = *(const uint32_t*)&As[r + 8][k0 + tg + 8];
        }
        uint32_t b[8][2];
#pragma unroll
        for (int f = 0; f < 8; f++) {
            int n = wn + f * 8 + g;
            b[f][0] = *(const uint32_t*)&Wsh[n][k0 + tg];
            b[f][1] = *(const uint32_t*)&Wsh[n][k0 + tg + 8];
        }
#pragma unroll
        for (int m = 0; m < 2; m++)
#pragma unroll
            for (int f = 0; f < 8; f++)
                mma_f16(acc[m][f], a[m], b[f]);
    }

#pragma unroll
    for (int m = 0; m < 2; m++) {
        int ra = row0 + wm + m * 16 + g;
        int rb = ra + 8;
        float sa = ns[ra];
        float sb = ns[rb];
        if (FINAL) { sa *= cf[ra]; sb *= cf[rb]; }
#pragma unroll
        for (int f = 0; f < 8; f++) {
            int n  = wn + f * 8 + tg;
            float b0 = __ldg(bias + n);
            float b1 = __ldg(bias + n + 1);
            float v0 = fmaxf(acc[m][f][0] + b0, 0.0f) * sa;
            float v1 = fmaxf(acc[m][f][1] + b1, 0.0f) * sa;
            float v2 = fmaxf(acc[m][f][2] + b0, 0.0f) * sb;
            float v3 = fmaxf(acc[m][f][3] + b1, 0.0f) * sb;
            if (!FINAL) {
                *(__half2*)(Out + (size_t)ra * DD + n) = __floats2half2_rn(v0, v1);
                *(__half2*)(Out + (size_t)rb * DD + n) = __floats2half2_rn(v2, v3);
            } else {
                float c0 = v0 + v2;
                float c1 = v1 + v3;
#pragma unroll
                for (int o = 4; o < 32; o <<= 1) {
                    c0 += __shfl_xor_sync(0xffffffff, c0, o);
                    c1 += __shfl_xor_sync(0xffffffff, c1, o);
                }
                if (g == 0) {
                    atomicAdd(&sv[n], c0);
                    atomicAdd(&sv[n + 1], c1);
                }
            }
        }
    }

    if (FINAL) {
        __syncthreads();
        if (t < DD) atomicAdd(&vec[t], sv[t]);
    }
}

// ------------------------- final micro-GEMM: out = (vec/N) @ W2 + b2 -------
__global__ void final_kernel(const float* __restrict__ W2,
                             const float* __restrict__ b2,
                             const float* __restrict__ vec,
                             float* __restrict__ out) {
    __shared__ float v[DD];
    int c = threadIdx.x;
    v[c] = vec[c] * (1.0f / (float)NN);
    __syncthreads();
    float acc = b2[c];
#pragma unroll 8
    for (int k = 0; k < DD; k++)
        acc = fmaf(v[k], W2[(size_t)k * DD + c], acc);
    out[c] = acc;
}

// ------------------------- stream/event infra (created at load time) -------
static cudaStream_t g_s2 = nullptr;
static cudaEvent_t  g_evA = nullptr, g_evB = nullptr, g_evC = nullptr;
static bool g_infraTried = false;

static void ensure_infra() {
    if (g_infraTried) return;
    g_infraTried = true;
    cudaStreamCreateWithFlags(&g_s2, cudaStreamNonBlocking);
    cudaEventCreateWithFlags(&g_evA, cudaEventDisableTiming);
    cudaEventCreateWithFlags(&g_evB, cudaEventDisableTiming);
    cudaEventCreateWithFlags(&g_evC, cudaEventDisableTiming);
}

namespace { struct InfraInit { InfraInit() { ensure_infra(); } } g_infraInit; }

// ===========================================================================
extern "C" void kernel_launch(void* const* d_in, const int* in_sizes, int n_in,
                              void* d_out, int out_size) {
    const float* h   = (const float*)d_in[0];
    const int*   src = (const int*)d_in[1];   // JAX demotes int64 -> int32
    const int*   dst = (const int*)d_in[2];
    const float* W0 = (const float*)d_in[3];
    const float* b0 = (const float*)d_in[4];
    const float* W1 = (const float*)d_in[5];
    const float* b1 = (const float*)d_in[6];
    const float* W2 = (const float*)d_in[7];
    const float* b2 = (const float*)d_in[8];
    float* out = (float*)d_out;

    void *pX, *pY, *pAGG, *pns, *pnd, *pc, *pcnt2, *pincl, *pcur, *pesrc,
         *pbsum, *pvec, *pWt0, *pWt1;
    cudaGetSymbolAddress(&pX,    g_X);
    cudaGetSymbolAddress(&pY,    g_Y);
    cudaGetSymbolAddress(&pAGG,  g_AGG);
    cudaGetSymbolAddress(&pns,   g_ns);
    cudaGetSymbolAddress(&pnd,   g_nd);
    cudaGetSymbolAddress(&pc,    g_c);
    cudaGetSymbolAddress(&pcnt2, g_cnt2);
    cudaGetSymbolAddress(&pincl, g_incl);
    cudaGetSymbolAddress(&pcur,  g_cur);
    cudaGetSymbolAddress(&pesrc, g_esrc);
    cudaGetSymbolAddress(&pbsum, g_bsum);
    cudaGetSymbolAddress(&pvec,  g_vec);
    cudaGetSymbolAddress(&pWt0,  g_Wt0);
    cudaGetSymbolAddress(&pWt1,  g_Wt1);
    __half* X    = (__half*)pX;
    __half* Y    = (__half*)pY;
    __half* AGG  = (__half*)pAGG;
    float*  ns   = (float*)pns;
    float*  nd   = (float*)pnd;
    float*  cf   = (float*)pc;
    int*    cnt2 = (int*)pcnt2;
    int*    incl = (int*)pincl;
    int*    cur  = (int*)pcur;
    int*    esrc = (int*)pesrc;
    int*    bsum = (int*)pbsum;
    float*  vec  = (float*)pvec;
    __half* Wt0  = (__half*)pWt0;
    __half* Wt1  = (__half*)pWt1;

    static int smemSet = 0;
    const int gemmSmem = 2 * 128 * SPAD * sizeof(__half);   // 69632 B
    if (!smemSet) {
        cudaFuncSetAttribute(gemm_f16_kernel<0>,
                             cudaFuncAttributeMaxDynamicSharedMemorySize, gemmSmem);
        cudaFuncSetAttribute(gemm_f16_kernel<1>,
                             cudaFuncAttributeMaxDynamicSharedMemorySize, gemmSmem);
        smemSet = 1;
    }

    const bool fork = (g_s2 != nullptr && g_evA && g_evB && g_evC);
    const int nScanBlocks = (NN + 1023) / 1024;   // 98

    // --- degrees ---
    cudaMemsetAsync(cnt2, 0, 2 * NN * sizeof(int));
    hist_kernel<<<(NE + 255) / 256, 256>>>(src, dst, cnt2);

    if (fork) {
        cudaEventRecord(g_evA, 0);
        cudaStreamWaitEvent(g_s2, g_evA, 0);
        // side stream: norms -> cf -> conv -> prep
        cudaMemsetAsync(cf, 0, NN * sizeof(float), g_s2);
        norm_kernel<<<(NN + 255) / 256, 256, 0, g_s2>>>(cnt2, ns, nd);
        cudaEventRecord(g_evB, g_s2);
        cf_kernel<<<(NE + 255) / 256, 256, 0, g_s2>>>(src, dst, nd, cf);
        conv_kernel<<<(NN * DD / 4 + 255) / 256, 256, 0, g_s2>>>(h, ns, X);
        prep_kernel<<<64, 256, 0, g_s2>>>(W0, W1, Wt0, Wt1);
        cudaEventRecord(g_evC, g_s2);
    } else {
        cudaMemsetAsync(cf, 0, NN * sizeof(float));
        norm_kernel<<<(NN + 255) / 256, 256>>>(cnt2, ns, nd);
        cf_kernel<<<(NE + 255) / 256, 256>>>(src, dst, nd, cf);
        conv_kernel<<<(NN * DD / 4 + 255) / 256, 256>>>(h, ns, X);
        prep_kernel<<<64, 256>>>(W0, W1, Wt0, Wt1);
    }

    // --- CSR chain on main stream ---
    scan1_kernel<<<nScanBlocks, 256>>>(cnt2 + NN, incl, bsum);
    scan3_kernel<<<nScanBlocks, 256>>>(incl, bsum, cnt2, cur);
    fill_kernel<<<(NE + 255) / 256, 256>>>(src, dst, cur, esrc);
    if (fork) cudaStreamWaitEvent(0, g_evC, 0);   // gather0 needs X; gemm needs Wt, cf

    const int gatherBlocks = (NN * 32 + 255) / 256;   // 12500
    const int gemmBlocks   = NN_PAD / 128;            // 782

    // --- layer 0: X -gather-> AGG -gemm-> Y ---
    gather_kernel<<<gatherBlocks, 256>>>(X, nd, incl, cnt2, esrc, AGG);
    gemm_f16_kernel<0><<<gemmBlocks, 256, gemmSmem>>>(AGG, Wt0, b0, ns, cf, Y, vec);

    // --- layer 1 + folded layer 2: Y -gather-> AGG -gemm+reduce-> vec ---
    gather_kernel<<<gatherBlocks, 256>>>(Y, nd, incl, cnt2, esrc, AGG);
    cudaMemsetAsync(vec, 0, DD * sizeof(float));
    gemm_f16_kernel<1><<<gemmBlocks, 256, gemmSmem>>>(AGG, Wt1, b1, ns, cf, X, vec);

    // --- out = (vec/N) @ W2 + b2 ---
    final_kernel<<<1, DD>>>(W2, b2, vec, out);

    (void)in_sizes; (void)n_in; (void)out_size;
}